// round 12
// baseline (speedup 1.0000x reference)
#include <cuda_runtime.h>
#include <cuda_bf16.h>
#include <cstdint>

#define N_TOTAL   32768
#define K_CODES   8192
#define C_DIM     256
#define S_SPATIAL 4096
#define CS        (C_DIM * S_SPATIAL)
#define OUT_Z_ELEMS 8388608

#define M_CTA   256
#define NCH     64
#define NCHUNKS (K_CODES / NCH)     // 128
#define TAU     2.0e-4f
#define ROWPAD  264                  // bf16 elems per padded row (528 B)

// dynamic smem map (bytes)
#define SM_CNS   0                   // float[2][64]
#define SM_A     1024                // 256 * 528 = 135168
#define SM_B0    (SM_A + 135168)     // 64 * 528 = 33792
#define SM_B1    (SM_B0 + 33792)
#define SMEM_BYTES (SM_B1 + 33792)   // 203776

__device__ float g_znorm[N_TOTAL];
__device__ float g_cnorm[K_CODES];
__device__ int   g_idx[N_TOTAL];
__device__ __align__(16) __nv_bfloat16 g_cb16[K_CODES * C_DIM];
__device__ int   g_fix_cnt, g_fs_cnt;
__device__ int   g_fix_row[N_TOTAL];
__device__ int   g_fix_n[N_TOTAL];
__device__ int   g_fix_cand[N_TOTAL][16];
__device__ int   g_fs_row[N_TOTAL];

// ---------- PTX helpers (all sm_80-era: legal at compute_103) ----------
__device__ __forceinline__ uint32_t smem_u32(const void* p) {
    uint32_t a;
    asm("{ .reg .u64 t; cvta.to.shared.u64 t, %1; cvt.u32.u64 %0, t; }" : "=r"(a) : "l"(p));
    return a;
}
__device__ __forceinline__ void ldmx4(uint32_t* r, uint32_t addr) {
    asm volatile("ldmatrix.sync.aligned.m8n8.x4.shared.b16 {%0,%1,%2,%3}, [%4];"
                 : "=r"(r[0]), "=r"(r[1]), "=r"(r[2]), "=r"(r[3]) : "r"(addr));
}
__device__ __forceinline__ void mma16816(float* d, const uint32_t* a,
                                         uint32_t b0, uint32_t b1) {
    asm volatile("mma.sync.aligned.m16n8k16.row.col.f32.bf16.bf16.f32 "
                 "{%0,%1,%2,%3}, {%4,%5,%6,%7}, {%8,%9}, {%0,%1,%2,%3};"
                 : "+f"(d[0]), "+f"(d[1]), "+f"(d[2]), "+f"(d[3])
                 : "r"(a[0]), "r"(a[1]), "r"(a[2]), "r"(a[3]), "r"(b0), "r"(b1));
}
__device__ __forceinline__ void cpasync16(uint32_t dst, const void* src) {
    asm volatile("cp.async.ca.shared.global [%0], [%1], 16;" :: "r"(dst), "l"(src));
}

// ---------- setup ----------
__global__ void init_kernel(float* loss) { *loss = 0.0f; g_fix_cnt = 0; g_fs_cnt = 0; }

__global__ void norms_kernel(const float* __restrict__ z, const float* __restrict__ cb) {
    if (blockIdx.x < 256) {
        int n0 = blockIdx.x * 128, b = n0 >> 12, s0 = n0 & 4095;
        const float* zr = z + (size_t)b * CS + s0 + threadIdx.x;
        float sum = 0.0f;
        #pragma unroll 8
        for (int c = 0; c < C_DIM; c++) { float v = zr[(size_t)c * S_SPATIAL]; sum += v * v; }
        g_znorm[n0 + threadIdx.x] = sum;
    } else {
        int k = (blockIdx.x - 256) * 128 + threadIdx.x;
        const float4* cr = (const float4*)(cb + (size_t)k * C_DIM);
        float sum = 0.0f;
        #pragma unroll 8
        for (int i = 0; i < C_DIM / 4; i++) {
            float4 v = cr[i];
            sum += v.x * v.x + v.y * v.y + v.z * v.z + v.w * v.w;
        }
        g_cnorm[k] = sum;
    }
}

__global__ void cb16_kernel(const float* __restrict__ cb) {
    int i = blockIdx.x * 1024 + threadIdx.x;
    g_cb16[i] = __float2bfloat16_rn(cb[i]);
}

// ---------- main: mma.sync bf16 GEMM, 16 warps = 8 m-pos x 2 n-halves ----------
__global__ void __launch_bounds__(512, 1)
argmin_mma_kernel(const float* __restrict__ z, float* __restrict__ out_idx_f) {
    extern __shared__ char sm[];
    uint32_t smb = smem_u32(sm);
    int tid = threadIdx.x;
    int w = tid >> 5, l = tid & 31;           // 16 warps
    int wm = w >> 1, wn = w & 1;              // m-position (0..7), n-half (0..1)
    int n0 = blockIdx.x * M_CTA;
    int b = n0 >> 12, s0 = n0 & 4095;
    float* cns = (float*)(sm + SM_CNS);

    // ---- fill A: 256 rows x 256 ch bf16, padded rows of 264; 2 threads/row ----
    {
        __nv_bfloat16* A = (__nv_bfloat16*)(sm + SM_A);
        int row = tid & 255;
        int ch0 = (tid >> 8) * 128;
        const float* zp = z + (size_t)b * CS + s0 + row;
        #pragma unroll 4
        for (int c = ch0; c < ch0 + 128; c += 2) {
            float v0 = zp[(size_t)c << 12];
            float v1 = zp[(size_t)(c + 1) << 12];
            __nv_bfloat162 pk;
            pk.x = __float2bfloat16_rn(v0);
            pk.y = __float2bfloat16_rn(v1);
            *(__nv_bfloat162*)&A[row * ROWPAD + c] = pk;
        }
    }

    // per-thread row norms for 4 row-slots: slot = mt*2 + half8
    // row = wm*32 + mt*16 + half8*8 + l/4
    float zn4[4];
    #pragma unroll
    for (int s = 0; s < 4; s++)
        zn4[s] = g_znorm[n0 + wm * 32 + (s >> 1) * 16 + (s & 1) * 8 + (l >> 2)];

    // ldmatrix base addresses (bytes)
    uint32_t aoff0 = smb + SM_A + (uint32_t)((wm * 32 + (l & 15)) * 528 + (l >> 4) * 16);
    uint32_t aoff1 = aoff0 + 16u * 528u;
    uint32_t bofs0 = (uint32_t)((wn * 32 + (l & 15)) * 528 + (l >> 4) * 16);
    uint32_t bofs1 = bofs0 + 16u * 528u;

    // best-4 per row-slot
    float bS[4][4]; int bI[4][4];
    #pragma unroll
    for (int s = 0; s < 4; s++)
        #pragma unroll
        for (int k = 0; k < 4; k++) { bS[s][k] = 3.4e38f; bI[s][k] = 0; }

    auto stage = [&](int chunk) {
        const __nv_bfloat16* src = g_cb16 + (size_t)chunk * NCH * C_DIM;
        uint32_t bb = smb + (uint32_t)((chunk & 1) ? SM_B1 : SM_B0);
        #pragma unroll
        for (int t = 0; t < 4; t++) {
            int idx = t * 512 + tid;           // 0..2047
            int code = idx >> 5, seg = idx & 31;
            cpasync16(bb + (uint32_t)(code * 528 + seg * 16),
                      src + (size_t)code * C_DIM + seg * 8);
        }
        if (tid < NCH) cns[(chunk & 1) * NCH + tid] = g_cnorm[chunk * NCH + tid];
        asm volatile("cp.async.commit_group;" ::: "memory");
    };

    stage(0);
    for (int i = 0; i < NCHUNKS; i++) {
        if (i + 1 < NCHUNKS) {
            stage(i + 1);
            asm volatile("cp.async.wait_group 1;" ::: "memory");
        } else {
            asm volatile("cp.async.wait_group 0;" ::: "memory");
        }
        __syncthreads();

        // ---- GEMM: D[32 rows x 32 codes] per warp, ks-pipelined fragments ----
        float acc[2][4][4];
        #pragma unroll
        for (int mt = 0; mt < 2; mt++)
            #pragma unroll
            for (int nt = 0; nt < 4; nt++)
                #pragma unroll
                for (int c = 0; c < 4; c++) acc[mt][nt][c] = 0.0f;

        uint32_t bsel = smb + (uint32_t)((i & 1) ? SM_B1 : SM_B0);
        uint32_t aF[2][2][4], bF[2][2][4];
        ldmx4(aF[0][0], aoff0);
        ldmx4(aF[0][1], aoff1);
        ldmx4(bF[0][0], bsel + bofs0);
        ldmx4(bF[0][1], bsel + bofs1);
        #pragma unroll
        for (int ks = 0; ks < 16; ks++) {
            int cur = ks & 1, nxt = cur ^ 1;
            if (ks < 15) {
                uint32_t ka = (uint32_t)((ks + 1) * 32);
                ldmx4(aF[nxt][0], aoff0 + ka);
                ldmx4(aF[nxt][1], aoff1 + ka);
                ldmx4(bF[nxt][0], bsel + bofs0 + ka);
                ldmx4(bF[nxt][1], bsel + bofs1 + ka);
            }
            #pragma unroll
            for (int p = 0; p < 2; p++) {
                mma16816(acc[0][2 * p],     aF[cur][0], bF[cur][p][0], bF[cur][p][2]);
                mma16816(acc[0][2 * p + 1], aF[cur][0], bF[cur][p][1], bF[cur][p][3]);
                mma16816(acc[1][2 * p],     aF[cur][1], bF[cur][p][0], bF[cur][p][2]);
                mma16816(acc[1][2 * p + 1], aF[cur][1], bF[cur][p][1], bF[cur][p][3]);
            }
        }

        // ---- epilogue: scores + best-4 insert ----
        const float* cn = cns + (i & 1) * NCH;
        int j0 = i * NCH;
        #pragma unroll
        for (int nt = 0; nt < 4; nt++) {
            int col0 = wn * 32 + nt * 8 + 2 * (l & 3);
            float2 cn2 = *(const float2*)&cn[col0];
            int id0 = j0 + col0;
            #pragma unroll
            for (int mt = 0; mt < 2; mt++) {
                #pragma unroll
                for (int c = 0; c < 4; c++) {
                    int slot = mt * 2 + (c >> 1);
                    float base = zn4[slot] + ((c & 1) ? cn2.y : cn2.x);
                    float s = fmaf(-2.0f, acc[mt][nt][c], base);
                    if (s < bS[slot][3]) {
                        int id = id0 + (c & 1);
                        #pragma unroll
                        for (int k = 0; k < 4; k++) {
                            if (s < bS[slot][k]) {
                                float ts = bS[slot][k]; int ti = bI[slot][k];
                                bS[slot][k] = s; bI[slot][k] = id;
                                s = ts; id = ti;
                            }
                        }
                    }
                }
            }
        }
        __syncthreads();
    }

    // ---- merge: per row 32 entries (2 n-half warps x 4 lanes x best-4) ----
    float* mergeS = (float*)(sm + SM_B0);            // 256*32*4 = 32768 B
    int*   mergeI = (int*)(sm + SM_B0 + 32768);      // 32768 B
    __syncthreads();
    #pragma unroll
    for (int s = 0; s < 4; s++) {
        int row = wm * 32 + (s >> 1) * 16 + (s & 1) * 8 + (l >> 2);
        int base = row * 32 + (wn * 4 + (l & 3)) * 4;
        #pragma unroll
        for (int k = 0; k < 4; k++) { mergeS[base + k] = bS[s][k]; mergeI[base + k] = bI[s][k]; }
    }
    __syncthreads();

    // ---- classify: one row per thread (threads 0..255) ----
    if (tid < 256) {
        int r = tid, base = r * 32, row = n0 + r;
        float mn = 3.4e38f;
        #pragma unroll
        for (int k = 0; k < 32; k++) mn = fminf(mn, mergeS[base + k]);
        float lim = mn + TAU;
        bool fs = false;
        #pragma unroll
        for (int q = 0; q < 8; q++) if (mergeS[base + q * 4 + 3] <= lim) fs = true;
        int cnt = 0; float bs = 3.4e38f; int bi = 0x7fffffff;
        #pragma unroll
        for (int k = 0; k < 32; k++) {
            float s = mergeS[base + k]; int id = mergeI[base + k];
            if (s <= lim) cnt++;
            if (s < bs || (s == bs && id < bi)) { bs = s; bi = id; }
        }
        if (cnt > 16) fs = true;
        if (fs) {
            int p = atomicAdd(&g_fs_cnt, 1);
            g_fs_row[p] = row;
        } else if (cnt == 1) {
            g_idx[row] = bi;
            out_idx_f[row] = (float)bi;
        } else {
            int p = atomicAdd(&g_fix_cnt, 1);
            g_fix_row[p] = row; g_fix_n[p] = cnt;
            int c2 = 0;
            for (int k = 0; k < 32 && c2 < 16; k++)
                if (mergeS[base + k] <= lim) g_fix_cand[p][c2++] = mergeI[base + k];
        }
    }
}

// ---------- fixups (exact reference fp32 chain) ----------
__global__ void fixup_cand_kernel(const float* __restrict__ z, const float* __restrict__ cb,
                                  float* __restrict__ out_idx_f) {
    int cnt = g_fix_cnt;
    int wid = threadIdx.x >> 5, lid = threadIdx.x & 31;
    for (int rec = blockIdx.x * 4 + wid; rec < cnt; rec += gridDim.x * 4) {
        int row = g_fix_row[rec], nc = g_fix_n[rec];
        float s = 3.4e38f; int ci = 0x7fffffff;
        if (lid < nc) {
            ci = g_fix_cand[rec][lid];
            const float* zr = z + (size_t)(row >> 12) * CS + (row & 4095);
            const float* cr = cb + (size_t)ci * C_DIM;
            float dot = 0.0f;
            #pragma unroll 8
            for (int c = 0; c < C_DIM; c++) dot = fmaf(zr[(size_t)c << 12], cr[c], dot);
            s = __fadd_rn(__fadd_rn(g_znorm[row], g_cnorm[ci]), -2.0f * dot);
        }
        #pragma unroll
        for (int off = 16; off > 0; off >>= 1) {
            float so = __shfl_down_sync(0xffffffffu, s, off);
            int   io = __shfl_down_sync(0xffffffffu, ci, off);
            if (so < s || (so == s && io < ci)) { s = so; ci = io; }
        }
        if (lid == 0) { g_idx[row] = ci; out_idx_f[row] = (float)ci; }
    }
}

__global__ void fullscan_kernel(const float* __restrict__ z, const float* __restrict__ cb,
                                float* __restrict__ out_idx_f) {
    __shared__ float zrow[C_DIM];
    __shared__ float sS[256]; __shared__ int sI[256];
    int cnt = g_fs_cnt, tid = threadIdx.x;
    for (int q = blockIdx.x; q < cnt; q += gridDim.x) {
        int row = g_fs_row[q];
        const float* zr = z + (size_t)(row >> 12) * CS + (row & 4095);
        zrow[tid] = zr[(size_t)tid << 12];
        __syncthreads();
        float zn = g_znorm[row];
        float bs = 3.4e38f; int bi = 0;
        for (int j = tid; j < K_CODES; j += 256) {
            const float* cr = cb + (size_t)j * C_DIM;
            float dot = 0.0f;
            #pragma unroll 8
            for (int c = 0; c < C_DIM; c++) dot = fmaf(zrow[c], cr[c], dot);
            float s = __fadd_rn(__fadd_rn(zn, g_cnorm[j]), -2.0f * dot);
            if (s < bs) { bs = s; bi = j; }
        }
        sS[tid] = bs; sI[tid] = bi;
        __syncthreads();
        for (int off = 128; off > 0; off >>= 1) {
            if (tid < off) {
                float s2 = sS[tid + off]; int i2 = sI[tid + off];
                if (s2 < sS[tid] || (s2 == sS[tid] && i2 < sI[tid])) { sS[tid] = s2; sI[tid] = i2; }
            }
            __syncthreads();
        }
        if (tid == 0) { g_idx[row] = sI[0]; out_idx_f[row] = (float)sI[0]; }
        __syncthreads();
    }
}

// ---------- gather + loss ----------
__global__ void gather_loss_kernel(const float* __restrict__ z, const float* __restrict__ cb,
                                   float* __restrict__ out, float* __restrict__ loss) {
    int tid = threadIdx.x;
    int n = blockIdx.x * 256 + tid;
    int b = n >> 12, s = n & 4095;
    int ci = g_idx[n];
    const float* zr = z + (size_t)b * CS + s;
    float* orow = out + (size_t)b * CS + s;
    const float4* cr = (const float4*)(cb + (size_t)ci * C_DIM);

    float sum = 0.0f;
    #pragma unroll 4
    for (int c4 = 0; c4 < C_DIM / 4; c4++) {
        float4 q = cr[c4];
        size_t base = (size_t)(c4 * 4) * S_SPATIAL;
        float z0 = zr[base], z1 = zr[base + S_SPATIAL];
        float z2 = zr[base + 2 * S_SPATIAL], z3 = zr[base + 3 * S_SPATIAL];
        float d0 = __fadd_rn(q.x, -z0), d1 = __fadd_rn(q.y, -z1);
        float d2 = __fadd_rn(q.z, -z2), d3 = __fadd_rn(q.w, -z3);
        orow[base]                 = __fadd_rn(z0, d0);
        orow[base + S_SPATIAL]     = __fadd_rn(z1, d1);
        orow[base + 2 * S_SPATIAL] = __fadd_rn(z2, d2);
        orow[base + 3 * S_SPATIAL] = __fadd_rn(z3, d3);
        sum += d0 * d0 + d1 * d1 + d2 * d2 + d3 * d3;
    }
    __shared__ float wsum[8];
    #pragma unroll
    for (int off = 16; off > 0; off >>= 1) sum += __shfl_down_sync(0xffffffffu, sum, off);
    if ((tid & 31) == 0) wsum[tid >> 5] = sum;
    __syncthreads();
    if (tid == 0) {
        float t = 0.0f;
        #pragma unroll
        for (int w = 0; w < 8; w++) t += wsum[w];
        atomicAdd(loss, t * (2.0f / (float)(N_TOTAL * C_DIM)));
    }
}

extern "C" void kernel_launch(void* const* d_in, const int* in_sizes, int n_in,
                              void* d_out, int out_size) {
    (void)in_sizes; (void)n_in; (void)out_size;
    const float* z  = (const float*)d_in[0];
    const float* cb = (const float*)d_in[1];
    float* out  = (float*)d_out;
    float* loss = out + OUT_Z_ELEMS;
    float* idxf = out + OUT_Z_ELEMS + 1;

    // Not a stream op: safe under graph capture, idempotent, no static state.
    cudaFuncSetAttribute(argmin_mma_kernel,
                         cudaFuncAttributeMaxDynamicSharedMemorySize, SMEM_BYTES);

    init_kernel<<<1, 1>>>(loss);
    norms_kernel<<<320, 128>>>(z, cb);
    cb16_kernel<<<2048, 1024>>>(cb);
    argmin_mma_kernel<<<128, 512, SMEM_BYTES>>>(z, idxf);
    fixup_cand_kernel<<<256, 128>>>(z, cb, idxf);
    fullscan_kernel<<<64, 256>>>(z, cb, idxf);
    gather_loss_kernel<<<128, 256>>>(z, cb, out, loss);
}

// round 13
// speedup vs baseline: 1.0139x; 1.0139x over previous
#include <cuda_runtime.h>
#include <cuda_bf16.h>
#include <cstdint>

#define N_TOTAL   32768
#define K_CODES   8192
#define C_DIM     256
#define S_SPATIAL 4096
#define CS        (C_DIM * S_SPATIAL)
#define OUT_Z_ELEMS 8388608

#define M_CTA   256
#define NCH     32
#define NCHUNKS (K_CODES / NCH)     // 256 total; 128 per group
#define TAU     2.0e-4f
#define ROWPAD  264                  // bf16 elems per padded row (528 B)
#define BBYTES  16896                // 32 codes * 528 B

// dynamic smem map (bytes)
#define SM_CNS   0                   // float[4][32]  (group*2+buf)
#define SM_A     1024                // 256 * 528 = 135168
#define SM_B     (SM_A + 135168)     // 4 buffers of 16896 = 67584
#define SMEM_BYTES (SM_B + 4 * BBYTES)   // 203776

__device__ float g_znorm[N_TOTAL];
__device__ float g_cnorm[K_CODES];
__device__ int   g_idx[N_TOTAL];
__device__ __align__(16) __nv_bfloat16 g_cb16[K_CODES * C_DIM];
__device__ int   g_fix_cnt, g_fs_cnt;
__device__ int   g_fix_row[N_TOTAL];
__device__ int   g_fix_n[N_TOTAL];
__device__ int   g_fix_cand[N_TOTAL][16];
__device__ int   g_fs_row[N_TOTAL];

// ---------- PTX helpers (all sm_80-era: legal at compute_103) ----------
__device__ __forceinline__ uint32_t smem_u32(const void* p) {
    uint32_t a;
    asm("{ .reg .u64 t; cvta.to.shared.u64 t, %1; cvt.u32.u64 %0, t; }" : "=r"(a) : "l"(p));
    return a;
}
__device__ __forceinline__ void ldmx4(uint32_t* r, uint32_t addr) {
    asm volatile("ldmatrix.sync.aligned.m8n8.x4.shared.b16 {%0,%1,%2,%3}, [%4];"
                 : "=r"(r[0]), "=r"(r[1]), "=r"(r[2]), "=r"(r[3]) : "r"(addr));
}
__device__ __forceinline__ void mma16816(float* d, const uint32_t* a,
                                         uint32_t b0, uint32_t b1) {
    asm volatile("mma.sync.aligned.m16n8k16.row.col.f32.bf16.bf16.f32 "
                 "{%0,%1,%2,%3}, {%4,%5,%6,%7}, {%8,%9}, {%0,%1,%2,%3};"
                 : "+f"(d[0]), "+f"(d[1]), "+f"(d[2]), "+f"(d[3])
                 : "r"(a[0]), "r"(a[1]), "r"(a[2]), "r"(a[3]), "r"(b0), "r"(b1));
}
__device__ __forceinline__ void cpasync16(uint32_t dst, const void* src) {
    asm volatile("cp.async.ca.shared.global [%0], [%1], 16;" :: "r"(dst), "l"(src));
}
__device__ __forceinline__ void barsync(int id, int cnt) {
    asm volatile("bar.sync %0, %1;" :: "r"(id), "r"(cnt) : "memory");
}

// ---------- setup ----------
__global__ void init_kernel(float* loss) { *loss = 0.0f; g_fix_cnt = 0; g_fs_cnt = 0; }

__global__ void norms_kernel(const float* __restrict__ z, const float* __restrict__ cb) {
    if (blockIdx.x < 256) {
        int n0 = blockIdx.x * 128, b = n0 >> 12, s0 = n0 & 4095;
        const float* zr = z + (size_t)b * CS + s0 + threadIdx.x;
        float sum = 0.0f;
        #pragma unroll 8
        for (int c = 0; c < C_DIM; c++) { float v = zr[(size_t)c * S_SPATIAL]; sum += v * v; }
        g_znorm[n0 + threadIdx.x] = sum;
    } else {
        int k = (blockIdx.x - 256) * 128 + threadIdx.x;
        const float4* cr = (const float4*)(cb + (size_t)k * C_DIM);
        float sum = 0.0f;
        #pragma unroll 8
        for (int i = 0; i < C_DIM / 4; i++) {
            float4 v = cr[i];
            sum += v.x * v.x + v.y * v.y + v.z * v.z + v.w * v.w;
        }
        g_cnorm[k] = sum;
    }
}

__global__ void cb16_kernel(const float* __restrict__ cb) {
    int i = blockIdx.x * 1024 + threadIdx.x;
    g_cb16[i] = __float2bfloat16_rn(cb[i]);
}

// ---------- main: two independent 8-warp GEMM pipelines per CTA ----------
__global__ void __launch_bounds__(512, 1)
argmin_mma_kernel(const float* __restrict__ z, float* __restrict__ out_idx_f) {
    extern __shared__ char sm[];
    uint32_t smb = smem_u32(sm);
    int tid = threadIdx.x;
    int w = tid >> 5, l = tid & 31;
    int g  = w >> 3;                 // group 0: even chunks, group 1: odd chunks
    int wm = w & 7;                  // m-position within group (8 x 32 rows)
    int gl = tid & 255;              // group-local thread id
    int n0 = blockIdx.x * M_CTA;
    int b = n0 >> 12, s0 = n0 & 4095;
    float* cns = (float*)(sm + SM_CNS);   // [4][32]

    // ---- fill A: 256 rows x 256 ch bf16, padded rows of 264; 2 threads/row ----
    {
        __nv_bfloat16* A = (__nv_bfloat16*)(sm + SM_A);
        int row = tid & 255;
        int ch0 = (tid >> 8) * 128;
        const float* zp = z + (size_t)b * CS + s0 + row;
        #pragma unroll 4
        for (int c = ch0; c < ch0 + 128; c += 2) {
            float v0 = zp[(size_t)c << 12];
            float v1 = zp[(size_t)(c + 1) << 12];
            __nv_bfloat162 pk;
            pk.x = __float2bfloat16_rn(v0);
            pk.y = __float2bfloat16_rn(v1);
            *(__nv_bfloat162*)&A[row * ROWPAD + c] = pk;
        }
    }

    // row norms: slot s -> row = wm*32 + (s>>1)*16 + (s&1)*8 + l/4
    float zn4[4];
    #pragma unroll
    for (int s = 0; s < 4; s++)
        zn4[s] = g_znorm[n0 + wm * 32 + (s >> 1) * 16 + (s & 1) * 8 + (l >> 2)];

    // ldmatrix base addresses
    uint32_t aoff0 = smb + SM_A + (uint32_t)((wm * 32 + (l & 15)) * 528 + (l >> 4) * 16);
    uint32_t aoff1 = aoff0 + 16u * 528u;
    uint32_t bbase = smb + SM_B + (uint32_t)(g * 2 * BBYTES);
    uint32_t bofs0 = (uint32_t)((l & 15) * 528 + (l >> 4) * 16);
    uint32_t bofs1 = bofs0 + 16u * 528u;

    // best-4 per row-slot
    float bS[4][4]; int bI[4][4];
    #pragma unroll
    for (int s = 0; s < 4; s++)
        #pragma unroll
        for (int k = 0; k < 4; k++) { bS[s][k] = 3.4e38f; bI[s][k] = 0; }

    // stage group-chunk k (global chunk = g + 2k) into buffer k&1
    auto stage = [&](int k) {
        int chunk = g + 2 * k;
        const __nv_bfloat16* src = g_cb16 + (size_t)chunk * NCH * C_DIM;
        uint32_t bb = bbase + (uint32_t)((k & 1) * BBYTES);
        #pragma unroll
        for (int t = 0; t < 4; t++) {
            int idx = t * 256 + gl;            // 0..1023
            int code = idx >> 5, seg = idx & 31;
            cpasync16(bb + (uint32_t)(code * 528 + seg * 16),
                      src + (size_t)code * C_DIM + seg * 8);
        }
        if (gl < NCH) cns[(g * 2 + (k & 1)) * NCH + gl] = g_cnorm[chunk * NCH + gl];
        asm volatile("cp.async.commit_group;" ::: "memory");
    };

    stage(0);
    stage(1);
    __syncthreads();     // A visible to all; initial cns ordering via group barrier below

    int barid = g + 1;
    for (int k = 0; k < 128; k++) {
        if (k < 126) { asm volatile("cp.async.wait_group 1;" ::: "memory"); }
        else         { asm volatile("cp.async.wait_group 0;" ::: "memory"); }
        barsync(barid, 256);

        // ---- GEMM: D[32 rows x 32 codes] per warp, ks-pipelined fragments ----
        float acc[2][4][4];
        #pragma unroll
        for (int mt = 0; mt < 2; mt++)
            #pragma unroll
            for (int nt = 0; nt < 4; nt++)
                #pragma unroll
                for (int c = 0; c < 4; c++) acc[mt][nt][c] = 0.0f;

        uint32_t bsel = bbase + (uint32_t)((k & 1) * BBYTES);
        uint32_t aF[2][2][4], bF[2][2][4];
        ldmx4(aF[0][0], aoff0);
        ldmx4(aF[0][1], aoff1);
        ldmx4(bF[0][0], bsel + bofs0);
        ldmx4(bF[0][1], bsel + bofs1);
        #pragma unroll
        for (int ks = 0; ks < 16; ks++) {
            int cur = ks & 1, nxt = cur ^ 1;
            if (ks < 15) {
                uint32_t ka = (uint32_t)((ks + 1) * 32);
                ldmx4(aF[nxt][0], aoff0 + ka);
                ldmx4(aF[nxt][1], aoff1 + ka);
                ldmx4(bF[nxt][0], bsel + bofs0 + ka);
                ldmx4(bF[nxt][1], bsel + bofs1 + ka);
            }
            #pragma unroll
            for (int p = 0; p < 2; p++) {
                mma16816(acc[0][2 * p],     aF[cur][0], bF[cur][p][0], bF[cur][p][2]);
                mma16816(acc[0][2 * p + 1], aF[cur][0], bF[cur][p][1], bF[cur][p][3]);
                mma16816(acc[1][2 * p],     aF[cur][1], bF[cur][p][0], bF[cur][p][2]);
                mma16816(acc[1][2 * p + 1], aF[cur][1], bF[cur][p][1], bF[cur][p][3]);
            }
        }

        // ---- epilogue: scores + best-4 insert ----
        const float* cn = cns + (g * 2 + (k & 1)) * NCH;
        int j0 = (g + 2 * k) * NCH;
        #pragma unroll
        for (int nt = 0; nt < 4; nt++) {
            int col0 = nt * 8 + 2 * (l & 3);
            float2 cn2 = *(const float2*)&cn[col0];
            int id0 = j0 + col0;
            #pragma unroll
            for (int mt = 0; mt < 2; mt++) {
                #pragma unroll
                for (int c = 0; c < 4; c++) {
                    int slot = mt * 2 + (c >> 1);
                    float base = zn4[slot] + ((c & 1) ? cn2.y : cn2.x);
                    float s = fmaf(-2.0f, acc[mt][nt][c], base);
                    if (s < bS[slot][3]) {
                        int id = id0 + (c & 1);
                        #pragma unroll
                        for (int kk = 0; kk < 4; kk++) {
                            if (s < bS[slot][kk]) {
                                float ts = bS[slot][kk]; int ti = bI[slot][kk];
                                bS[slot][kk] = s; bI[slot][kk] = id;
                                s = ts; id = ti;
                            }
                        }
                    }
                }
            }
        }

        barsync(barid, 256);       // group done reading buffer (k&1) and cns
        if (k + 2 < 128) stage(k + 2);
    }

    // ---- merge: per row 32 entries (2 groups x 4 lanes x best-4) ----
    float* mergeS = (float*)(sm + SM_B);            // 256*32*4 = 32768 B
    int*   mergeI = (int*)(sm + SM_B + 32768);      // 32768 B
    __syncthreads();
    #pragma unroll
    for (int s = 0; s < 4; s++) {
        int row = wm * 32 + (s >> 1) * 16 + (s & 1) * 8 + (l >> 2);
        int base = row * 32 + g * 16 + (l & 3) * 4;
        #pragma unroll
        for (int k = 0; k < 4; k++) { mergeS[base + k] = bS[s][k]; mergeI[base + k] = bI[s][k]; }
    }
    __syncthreads();

    // ---- classify: one row per thread (threads 0..255) ----
    if (tid < 256) {
        int r = tid, base = r * 32, row = n0 + r;
        float mn = 3.4e38f;
        #pragma unroll
        for (int k = 0; k < 32; k++) mn = fminf(mn, mergeS[base + k]);
        float lim = mn + TAU;
        bool fs = false;
        #pragma unroll
        for (int q = 0; q < 8; q++) if (mergeS[base + q * 4 + 3] <= lim) fs = true;
        int cnt = 0; float bs = 3.4e38f; int bi = 0x7fffffff;
        #pragma unroll
        for (int k = 0; k < 32; k++) {
            float s = mergeS[base + k]; int id = mergeI[base + k];
            if (s <= lim) cnt++;
            if (s < bs || (s == bs && id < bi)) { bs = s; bi = id; }
        }
        if (cnt > 16) fs = true;
        if (fs) {
            int p = atomicAdd(&g_fs_cnt, 1);
            g_fs_row[p] = row;
        } else if (cnt == 1) {
            g_idx[row] = bi;
            out_idx_f[row] = (float)bi;
        } else {
            int p = atomicAdd(&g_fix_cnt, 1);
            g_fix_row[p] = row; g_fix_n[p] = cnt;
            int c2 = 0;
            for (int k = 0; k < 32 && c2 < 16; k++)
                if (mergeS[base + k] <= lim) g_fix_cand[p][c2++] = mergeI[base + k];
        }
    }
}

// ---------- fixups (exact reference fp32 chain) ----------
__global__ void fixup_cand_kernel(const float* __restrict__ z, const float* __restrict__ cb,
                                  float* __restrict__ out_idx_f) {
    int cnt = g_fix_cnt;
    int wid = threadIdx.x >> 5, lid = threadIdx.x & 31;
    for (int rec = blockIdx.x * 4 + wid; rec < cnt; rec += gridDim.x * 4) {
        int row = g_fix_row[rec], nc = g_fix_n[rec];
        float s = 3.4e38f; int ci = 0x7fffffff;
        if (lid < nc) {
            ci = g_fix_cand[rec][lid];
            const float* zr = z + (size_t)(row >> 12) * CS + (row & 4095);
            const float* cr = cb + (size_t)ci * C_DIM;
            float dot = 0.0f;
            #pragma unroll 8
            for (int c = 0; c < C_DIM; c++) dot = fmaf(zr[(size_t)c << 12], cr[c], dot);
            s = __fadd_rn(__fadd_rn(g_znorm[row], g_cnorm[ci]), -2.0f * dot);
        }
        #pragma unroll
        for (int off = 16; off > 0; off >>= 1) {
            float so = __shfl_down_sync(0xffffffffu, s, off);
            int   io = __shfl_down_sync(0xffffffffu, ci, off);
            if (so < s || (so == s && io < ci)) { s = so; ci = io; }
        }
        if (lid == 0) { g_idx[row] = ci; out_idx_f[row] = (float)ci; }
    }
}

__global__ void fullscan_kernel(const float* __restrict__ z, const float* __restrict__ cb,
                                float* __restrict__ out_idx_f) {
    __shared__ float zrow[C_DIM];
    __shared__ float sS[256]; __shared__ int sI[256];
    int cnt = g_fs_cnt, tid = threadIdx.x;
    for (int q = blockIdx.x; q < cnt; q += gridDim.x) {
        int row = g_fs_row[q];
        const float* zr = z + (size_t)(row >> 12) * CS + (row & 4095);
        zrow[tid] = zr[(size_t)tid << 12];
        __syncthreads();
        float zn = g_znorm[row];
        float bs = 3.4e38f; int bi = 0;
        for (int j = tid; j < K_CODES; j += 256) {
            const float* cr = cb + (size_t)j * C_DIM;
            float dot = 0.0f;
            #pragma unroll 8
            for (int c = 0; c < C_DIM; c++) dot = fmaf(zrow[c], cr[c], dot);
            float s = __fadd_rn(__fadd_rn(zn, g_cnorm[j]), -2.0f * dot);
            if (s < bs) { bs = s; bi = j; }
        }
        sS[tid] = bs; sI[tid] = bi;
        __syncthreads();
        for (int off = 128; off > 0; off >>= 1) {
            if (tid < off) {
                float s2 = sS[tid + off]; int i2 = sI[tid + off];
                if (s2 < sS[tid] || (s2 == sS[tid] && i2 < sI[tid])) { sS[tid] = s2; sI[tid] = i2; }
            }
            __syncthreads();
        }
        if (tid == 0) { g_idx[row] = sI[0]; out_idx_f[row] = (float)sI[0]; }
        __syncthreads();
    }
}

// ---------- gather + loss ----------
__global__ void gather_loss_kernel(const float* __restrict__ z, const float* __restrict__ cb,
                                   float* __restrict__ out, float* __restrict__ loss) {
    int tid = threadIdx.x;
    int n = blockIdx.x * 256 + tid;
    int b = n >> 12, s = n & 4095;
    int ci = g_idx[n];
    const float* zr = z + (size_t)b * CS + s;
    float* orow = out + (size_t)b * CS + s;
    const float4* cr = (const float4*)(cb + (size_t)ci * C_DIM);

    float sum = 0.0f;
    #pragma unroll 4
    for (int c4 = 0; c4 < C_DIM / 4; c4++) {
        float4 q = cr[c4];
        size_t base = (size_t)(c4 * 4) * S_SPATIAL;
        float z0 = zr[base], z1 = zr[base + S_SPATIAL];
        float z2 = zr[base + 2 * S_SPATIAL], z3 = zr[base + 3 * S_SPATIAL];
        float d0 = __fadd_rn(q.x, -z0), d1 = __fadd_rn(q.y, -z1);
        float d2 = __fadd_rn(q.z, -z2), d3 = __fadd_rn(q.w, -z3);
        orow[base]                 = __fadd_rn(z0, d0);
        orow[base + S_SPATIAL]     = __fadd_rn(z1, d1);
        orow[base + 2 * S_SPATIAL] = __fadd_rn(z2, d2);
        orow[base + 3 * S_SPATIAL] = __fadd_rn(z3, d3);
        sum += d0 * d0 + d1 * d1 + d2 * d2 + d3 * d3;
    }
    __shared__ float wsum[8];
    #pragma unroll
    for (int off = 16; off > 0; off >>= 1) sum += __shfl_down_sync(0xffffffffu, sum, off);
    if ((tid & 31) == 0) wsum[tid >> 5] = sum;
    __syncthreads();
    if (tid == 0) {
        float t = 0.0f;
        #pragma unroll
        for (int w = 0; w < 8; w++) t += wsum[w];
        atomicAdd(loss, t * (2.0f / (float)(N_TOTAL * C_DIM)));
    }
}

extern "C" void kernel_launch(void* const* d_in, const int* in_sizes, int n_in,
                              void* d_out, int out_size) {
    (void)in_sizes; (void)n_in; (void)out_size;
    const float* z  = (const float*)d_in[0];
    const float* cb = (const float*)d_in[1];
    float* out  = (float*)d_out;
    float* loss = out + OUT_Z_ELEMS;
    float* idxf = out + OUT_Z_ELEMS + 1;

    // Not a stream op: safe under graph capture, idempotent, no static state.
    cudaFuncSetAttribute(argmin_mma_kernel,
                         cudaFuncAttributeMaxDynamicSharedMemorySize, SMEM_BYTES);

    init_kernel<<<1, 1>>>(loss);
    norms_kernel<<<320, 128>>>(z, cb);
    cb16_kernel<<<2048, 1024>>>(cb);
    argmin_mma_kernel<<<128, 512, SMEM_BYTES>>>(z, idxf);
    fixup_cand_kernel<<<256, 128>>>(z, cb, idxf);
    fullscan_kernel<<<64, 256>>>(z, cb, idxf);
    gather_loss_kernel<<<128, 256>>>(z, cb, out, loss);
}